// round 9
// baseline (speedup 1.0000x reference)
#include <cuda_runtime.h>
#include <cuda_bf16.h>
#include <math_constants.h>
#include <cstdint>

// Cross-entropy: mean over rows of (logsumexp(row) - row[target]).
// B=8192 rows, V=50257 cols, fp32 logits, int32 targets.
// Main kernel: one CTA per row, one-pass online logsumexp, float4 __ldcs
// streaming with misalignment prologue (row stride 50257*4B is 4B-aligned).
// ~88% DRAM / 7.0 TB/s -> near HBM ceiling.
// Final reduce launched via PDL (programmatic stream serialization): its grid
// setup overlaps the main grid's drain; griddepcontrol.wait guarantees
// g_row_loss visibility before the reduce reads it.

#define B_ROWS   8192
#define V_COLS   50257
#define THREADS  256
#define L2E      1.4426950408889634f   // log2(e)
#define INV_L2E  0.6931471805599453f   // ln(2)

__device__ float g_row_loss[B_ROWS];

__device__ __forceinline__ float ex2f(float x) {
    float y;
    asm("ex2.approx.ftz.f32 %0, %1;" : "=f"(y) : "f"(x));
    return y;
}

// Online update of (m, s) with element x, where s = sum_i 2^((x_i - m) * L2E).
// Single MUFU per element: e = 2^(-|x-m|*L2E), then predicated merge.
__device__ __forceinline__ void online_update(float x, float& m, float& s) {
    float d = x - m;
    float e = ex2f(-fabsf(d) * L2E);
    if (d > 0.0f) {          // new max: rescale old sum, add 1 for x itself
        s = fmaf(s, e, 1.0f);
        m = x;
    } else {                 // common case
        s += e;
    }
}

// Merge two (m, s) pairs.
__device__ __forceinline__ void online_merge(float mo, float so, float& m, float& s) {
    float M = fmaxf(m, mo);
    s = s * ex2f((m - M) * L2E) + so * ex2f((mo - M) * L2E);
    m = M;
}

__global__ __launch_bounds__(THREADS)
void ce_row_lse_kernel(const float* __restrict__ inp,
                       const int* __restrict__ tgt) {
    const int row = blockIdx.x;
    const float* rowp = inp + (long long)row * V_COLS;

    // Alignment split: pre scalars -> 16B-aligned vec4 region -> tail scalars.
    const int mis  = (int)((((uintptr_t)rowp) >> 2) & 3);   // misaligned floats
    const int pre  = (4 - mis) & 3;
    const int nvec = (V_COLS - pre) >> 2;
    const int tail = V_COLS - pre - (nvec << 2);
    const float4* p4 = reinterpret_cast<const float4*>(rowp + pre);

    float m = -CUDART_INF_F;
    float s = 0.0f;

    // Prologue scalars (0..3 elements).
    if (threadIdx.x < pre) {
        online_update(__ldcs(rowp + threadIdx.x), m, s);
    }

    // Vectorized streaming main loop.
    #pragma unroll 4
    for (int i = threadIdx.x; i < nvec; i += THREADS) {
        float4 v = __ldcs(p4 + i);
        online_update(v.x, m, s);
        online_update(v.y, m, s);
        online_update(v.z, m, s);
        online_update(v.w, m, s);
    }

    // Tail scalars (0..3 elements).
    if (threadIdx.x < tail) {
        online_update(__ldcs(rowp + pre + (nvec << 2) + threadIdx.x), m, s);
    }

    // Warp reduction of (m, s).
    #pragma unroll
    for (int off = 16; off > 0; off >>= 1) {
        float mo = __shfl_xor_sync(0xffffffffu, m, off);
        float so = __shfl_xor_sync(0xffffffffu, s, off);
        online_merge(mo, so, m, s);
    }

    // Cross-warp reduction via shared memory.
    __shared__ float sh_m[THREADS / 32];
    __shared__ float sh_s[THREADS / 32];
    const int wid = threadIdx.x >> 5;
    const int lid = threadIdx.x & 31;
    if (lid == 0) { sh_m[wid] = m; sh_s[wid] = s; }
    __syncthreads();

    if (threadIdx.x == 0) {
        m = sh_m[0]; s = sh_s[0];
        #pragma unroll
        for (int w = 1; w < THREADS / 32; ++w) {
            online_merge(sh_m[w], sh_s[w], m, s);
        }
        // lse (natural log) = m + ln(s) = m + log2(s) * ln(2)
        float lse = fmaf(__log2f(s), INV_L2E, m);
        int t = tgt[row];
        t = min(max(t, 0), V_COLS - 1);
        float picked = __ldg(rowp + t);
        g_row_loss[row] = lse - picked;
    }

    // Allow the dependent (reduce) grid to start launching while this grid
    // drains. Memory visibility is enforced by griddepcontrol.wait in the
    // dependent kernel, not by this trigger.
    asm volatile("griddepcontrol.launch_dependents;");
}

// Fast final mean: 1024 threads, each reads 2 independent float4s, then
// shuffle+smem tree. PDL: wait for the primary grid's memory to be visible.
__global__ __launch_bounds__(1024)
void ce_final_reduce_kernel(float* __restrict__ out) {
    asm volatile("griddepcontrol.wait;" ::: "memory");

    const float4* p4 = reinterpret_cast<const float4*>(g_row_loss);
    const int tid = threadIdx.x;

    float4 a = p4[tid];              // rows [4t, 4t+4)
    float4 b = p4[tid + 1024];       // rows [4096+4t, 4096+4t+4)
    float acc = (a.x + a.y) + (a.z + a.w) + (b.x + b.y) + (b.z + b.w);

    #pragma unroll
    for (int off = 16; off > 0; off >>= 1) {
        acc += __shfl_xor_sync(0xffffffffu, acc, off);
    }

    __shared__ float sh[32];
    const int wid = tid >> 5;
    const int lid = tid & 31;
    if (lid == 0) sh[wid] = acc;
    __syncthreads();

    if (wid == 0) {
        float v = sh[lid];
        #pragma unroll
        for (int off = 16; off > 0; off >>= 1) {
            v += __shfl_xor_sync(0xffffffffu, v, off);
        }
        if (lid == 0) {
            out[0] = v * (1.0f / (float)B_ROWS);
        }
    }
}

extern "C" void kernel_launch(void* const* d_in, const int* in_sizes, int n_in,
                              void* d_out, int out_size) {
    const float* inp = (const float*)d_in[0];
    const int* tgt = (const int*)d_in[1];
    float* out = (float*)d_out;

    ce_row_lse_kernel<<<B_ROWS, THREADS>>>(inp, tgt);

    // Launch the reduce with programmatic stream serialization (PDL): its
    // grid setup overlaps the primary grid's drain; the secondary kernel's
    // griddepcontrol.wait enforces the data dependency.
    cudaLaunchConfig_t cfg = {};
    cfg.gridDim = dim3(1, 1, 1);
    cfg.blockDim = dim3(1024, 1, 1);
    cfg.dynamicSmemBytes = 0;
    cfg.stream = 0;
    cudaLaunchAttribute attr[1];
    attr[0].id = cudaLaunchAttributeProgrammaticStreamSerialization;
    attr[0].val.programmaticStreamSerializationAllowed = 1;
    cfg.attrs = attr;
    cfg.numAttrs = 1;
    cudaLaunchKernelEx(&cfg, ce_final_reduce_kernel, out);
}

// round 10
// speedup vs baseline: 1.0150x; 1.0150x over previous
#include <cuda_runtime.h>
#include <cuda_bf16.h>
#include <math_constants.h>
#include <cstdint>

// Cross-entropy: mean over rows of (logsumexp(row) - row[target]).
// B=8192 rows, V=50257 cols, fp32 logits, int32 targets.
// Main kernel: one CTA per row, one-pass online logsumexp, float4 __ldcs
// streaming with misalignment prologue (row stride 50257*4B is 4B-aligned).
// ~88% DRAM / 7.0 TB/s -> near HBM ceiling.
// Final reduce: single cp.async.bulk (TMA) pulls all 32KB of row losses into
// smem (bypasses the single-SM LSU LDG issue floor that made the old reduce
// 4.2us), then LDS + shuffle tree.

#define B_ROWS   8192
#define V_COLS   50257
#define THREADS  256
#define L2E      1.4426950408889634f   // log2(e)
#define INV_L2E  0.6931471805599453f   // ln(2)

__device__ __align__(16) float g_row_loss[B_ROWS];

__device__ __forceinline__ float ex2f(float x) {
    float y;
    asm("ex2.approx.ftz.f32 %0, %1;" : "=f"(y) : "f"(x));
    return y;
}

// Online update of (m, s) with element x, where s = sum_i 2^((x_i - m) * L2E).
// Single MUFU per element: e = 2^(-|x-m|*L2E), then predicated merge.
__device__ __forceinline__ void online_update(float x, float& m, float& s) {
    float d = x - m;
    float e = ex2f(-fabsf(d) * L2E);
    if (d > 0.0f) {          // new max: rescale old sum, add 1 for x itself
        s = fmaf(s, e, 1.0f);
        m = x;
    } else {                 // common case
        s += e;
    }
}

// Merge two (m, s) pairs.
__device__ __forceinline__ void online_merge(float mo, float so, float& m, float& s) {
    float M = fmaxf(m, mo);
    s = s * ex2f((m - M) * L2E) + so * ex2f((mo - M) * L2E);
    m = M;
}

__global__ __launch_bounds__(THREADS)
void ce_row_lse_kernel(const float* __restrict__ inp,
                       const int* __restrict__ tgt) {
    const int row = blockIdx.x;
    const float* rowp = inp + (long long)row * V_COLS;

    // Alignment split: pre scalars -> 16B-aligned vec4 region -> tail scalars.
    const int mis  = (int)((((uintptr_t)rowp) >> 2) & 3);   // misaligned floats
    const int pre  = (4 - mis) & 3;
    const int nvec = (V_COLS - pre) >> 2;
    const int tail = V_COLS - pre - (nvec << 2);
    const float4* p4 = reinterpret_cast<const float4*>(rowp + pre);

    float m = -CUDART_INF_F;
    float s = 0.0f;

    // Prologue scalars (0..3 elements).
    if (threadIdx.x < pre) {
        online_update(__ldcs(rowp + threadIdx.x), m, s);
    }

    // Vectorized streaming main loop.
    #pragma unroll 4
    for (int i = threadIdx.x; i < nvec; i += THREADS) {
        float4 v = __ldcs(p4 + i);
        online_update(v.x, m, s);
        online_update(v.y, m, s);
        online_update(v.z, m, s);
        online_update(v.w, m, s);
    }

    // Tail scalars (0..3 elements).
    if (threadIdx.x < tail) {
        online_update(__ldcs(rowp + pre + (nvec << 2) + threadIdx.x), m, s);
    }

    // Warp reduction of (m, s).
    #pragma unroll
    for (int off = 16; off > 0; off >>= 1) {
        float mo = __shfl_xor_sync(0xffffffffu, m, off);
        float so = __shfl_xor_sync(0xffffffffu, s, off);
        online_merge(mo, so, m, s);
    }

    // Cross-warp reduction via shared memory.
    __shared__ float sh_m[THREADS / 32];
    __shared__ float sh_s[THREADS / 32];
    const int wid = threadIdx.x >> 5;
    const int lid = threadIdx.x & 31;
    if (lid == 0) { sh_m[wid] = m; sh_s[wid] = s; }
    __syncthreads();

    if (threadIdx.x == 0) {
        m = sh_m[0]; s = sh_s[0];
        #pragma unroll
        for (int w = 1; w < THREADS / 32; ++w) {
            online_merge(sh_m[w], sh_s[w], m, s);
        }
        // lse (natural log) = m + ln(s) = m + log2(s) * ln(2)
        float lse = fmaf(__log2f(s), INV_L2E, m);
        int t = tgt[row];
        t = min(max(t, 0), V_COLS - 1);
        float picked = __ldg(rowp + t);
        g_row_loss[row] = lse - picked;
    }
}

// Fast final mean: one cp.async.bulk pulls g_row_loss (32KB) into smem,
// then 1024 threads reduce via LDS.128 + shuffle/smem tree.
__global__ __launch_bounds__(1024)
void ce_final_reduce_kernel(float* __restrict__ out) {
    __shared__ __align__(16) float buf[B_ROWS];
    __shared__ __align__(8) unsigned long long mbar;
    const int tid = threadIdx.x;

    const uint32_t mbar_addr = (uint32_t)__cvta_generic_to_shared(&mbar);
    const uint32_t buf_addr  = (uint32_t)__cvta_generic_to_shared(buf);
    const uint32_t nbytes    = B_ROWS * sizeof(float);   // 32768

    if (tid == 0) {
        asm volatile("mbarrier.init.shared.b64 [%0], 1;" :: "r"(mbar_addr) : "memory");
        asm volatile("mbarrier.arrive.expect_tx.shared.b64 _, [%0], %1;"
                     :: "r"(mbar_addr), "r"(nbytes) : "memory");
        asm volatile(
            "cp.async.bulk.shared::cta.global.mbarrier::complete_tx::bytes [%0], [%1], %2, [%3];"
            :: "r"(buf_addr), "l"(g_row_loss), "r"(nbytes), "r"(mbar_addr)
            : "memory");
    }
    __syncthreads();   // mbarrier init visible to all before they wait

    // Wait for the bulk copy (phase 0).
    {
        uint32_t done;
        asm volatile(
            "{\n\t"
            ".reg .pred p;\n\t"
            "mbarrier.try_wait.parity.acquire.cta.shared::cta.b64 p, [%1], 0;\n\t"
            "selp.b32 %0, 1, 0, p;\n\t"
            "}"
            : "=r"(done) : "r"(mbar_addr) : "memory");
        if (!done) {
            asm volatile(
                "{\n\t"
                ".reg .pred P1;\n\t"
                "WL_%=:\n\t"
                "mbarrier.try_wait.parity.acquire.cta.shared::cta.b64 P1, [%0], 0, 0x989680;\n\t"
                "@P1 bra.uni WD_%=;\n\t"
                "bra.uni WL_%=;\n\t"
                "WD_%=:\n\t"
                "}"
                :: "r"(mbar_addr) : "memory");
        }
    }

    // Reduce from shared memory: each thread sums 8 values (2 x float4).
    const float4* p4 = reinterpret_cast<const float4*>(buf);
    float4 a = p4[tid];
    float4 b = p4[tid + 1024];
    float acc = (a.x + a.y) + (a.z + a.w) + (b.x + b.y) + (b.z + b.w);

    #pragma unroll
    for (int off = 16; off > 0; off >>= 1) {
        acc += __shfl_xor_sync(0xffffffffu, acc, off);
    }

    __shared__ float sh[32];
    const int wid = tid >> 5;
    const int lid = tid & 31;
    if (lid == 0) sh[wid] = acc;
    __syncthreads();

    if (wid == 0) {
        float v = sh[lid];
        #pragma unroll
        for (int off = 16; off > 0; off >>= 1) {
            v += __shfl_xor_sync(0xffffffffu, v, off);
        }
        if (lid == 0) {
            out[0] = v * (1.0f / (float)B_ROWS);
        }
    }
}

extern "C" void kernel_launch(void* const* d_in, const int* in_sizes, int n_in,
                              void* d_out, int out_size) {
    const float* inp = (const float*)d_in[0];
    const int* tgt = (const int*)d_in[1];
    float* out = (float*)d_out;

    ce_row_lse_kernel<<<B_ROWS, THREADS>>>(inp, tgt);
    ce_final_reduce_kernel<<<1, 1024>>>(out);
}